// round 2
// baseline (speedup 1.0000x reference)
#include <cuda_runtime.h>
#include <cstdint>

// Problem constants
constexpr int D_MODEL = 1024;
constexpr int D_SAE   = 16384;
constexpr int NROWS   = 8192;
constexpr int K_TOP   = 64;
constexpr int K_SEL   = 80;   // candidate pool for exact re-ranking
constexpr int K_BUF   = 96;   // candidate buffer (ties can push count past 80)

// ---------------------------------------------------------------------------
// Scratch (static __device__ arrays — no runtime allocation)
// ---------------------------------------------------------------------------
__device__ float g_WdT[(size_t)D_SAE * D_MODEL];   // 64 MB transposed decoder
__device__ int   g_cand_idx[(size_t)NROWS * K_BUF];
__device__ int   g_cand_cnt[NROWS];
__device__ int   g_tk_idx[NROWS * K_TOP];
__device__ float g_tk_val[NROWS * K_TOP];

// ---------------------------------------------------------------------------
// Kernel 1: W_dec [D_MODEL, D_SAE] -> g_WdT [D_SAE, D_MODEL]
// ---------------------------------------------------------------------------
__global__ void transpose_kernel(const float* __restrict__ Wd)
{
    __shared__ float tile[32][33];
    const int tx = threadIdx.x;           // 0..31
    const int ty = threadIdx.y;           // 0..7
    const int s0 = blockIdx.x * 32;       // D_SAE tile base
    const int d0 = blockIdx.y * 32;       // D_MODEL tile base

#pragma unroll
    for (int j = ty; j < 32; j += 8)
        tile[j][tx] = Wd[(size_t)(d0 + j) * D_SAE + (s0 + tx)];
    __syncthreads();
#pragma unroll
    for (int j = ty; j < 32; j += 8)
        g_WdT[(size_t)(s0 + j) * D_MODEL + (d0 + tx)] = tile[tx][j];
}

// ---------------------------------------------------------------------------
// Kernel 2: encoder GEMM (approximate pass)
// h[n,s] = relu( dot(x[n,:], W_enc[s,:]) + b_enc[s] )
// 128x128 tile, BK=8, 256 threads, 8x8 per thread, double-buffered smem.
// ---------------------------------------------------------------------------
__global__ __launch_bounds__(256, 2)
void encoder_gemm_kernel(const float* __restrict__ x,
                         const float* __restrict__ W,
                         const float* __restrict__ bias,
                         float* __restrict__ h)
{
    __shared__ float As[2][8][128];
    __shared__ float Bs[2][8][128];

    const int tid = threadIdx.x;
    const int tx  = tid & 15;      // 0..15 -> s microtile
    const int ty  = tid >> 4;      // 0..15 -> n microtile
    const int m0  = blockIdx.y * 128;
    const int s0  = blockIdx.x * 128;

    const int lrow = tid >> 1;          // 0..127
    const int lk4  = (tid & 1) * 4;     // 0 or 4

    const float* xg = x + (size_t)(m0 + lrow) * D_MODEL + lk4;
    const float* wg = W + (size_t)(s0 + lrow) * D_MODEL + lk4;

    float acc[8][8];
#pragma unroll
    for (int i = 0; i < 8; i++)
#pragma unroll
        for (int j = 0; j < 8; j++) acc[i][j] = 0.f;

    {
        float4 a4 = *(const float4*)xg;
        float4 b4 = *(const float4*)wg;
        As[0][lk4+0][lrow] = a4.x; As[0][lk4+1][lrow] = a4.y;
        As[0][lk4+2][lrow] = a4.z; As[0][lk4+3][lrow] = a4.w;
        Bs[0][lk4+0][lrow] = b4.x; Bs[0][lk4+1][lrow] = b4.y;
        Bs[0][lk4+2][lrow] = b4.z; Bs[0][lk4+3][lrow] = b4.w;
    }
    __syncthreads();

    const int NKT = D_MODEL / 8;  // 128
    for (int kt = 0; kt < NKT; kt++) {
        const int cur = kt & 1;
        float4 na, nb;
        if (kt + 1 < NKT) {
            na = *(const float4*)(xg + (kt + 1) * 8);
            nb = *(const float4*)(wg + (kt + 1) * 8);
        }
#pragma unroll
        for (int kk = 0; kk < 8; kk++) {
            float a[8], b[8];
            *(float4*)&a[0] = *(const float4*)&As[cur][kk][ty * 4];
            *(float4*)&a[4] = *(const float4*)&As[cur][kk][64 + ty * 4];
            *(float4*)&b[0] = *(const float4*)&Bs[cur][kk][tx * 4];
            *(float4*)&b[4] = *(const float4*)&Bs[cur][kk][64 + tx * 4];
#pragma unroll
            for (int i = 0; i < 8; i++)
#pragma unroll
                for (int j = 0; j < 8; j++)
                    acc[i][j] += a[i] * b[j];
        }
        if (kt + 1 < NKT) {
            const int nxt = cur ^ 1;
            As[nxt][lk4+0][lrow] = na.x; As[nxt][lk4+1][lrow] = na.y;
            As[nxt][lk4+2][lrow] = na.z; As[nxt][lk4+3][lrow] = na.w;
            Bs[nxt][lk4+0][lrow] = nb.x; Bs[nxt][lk4+1][lrow] = nb.y;
            Bs[nxt][lk4+2][lrow] = nb.z; Bs[nxt][lk4+3][lrow] = nb.w;
            __syncthreads();
        }
    }

    float bv[8];
    *(float4*)&bv[0] = *(const float4*)(bias + s0 + tx * 4);
    *(float4*)&bv[4] = *(const float4*)(bias + s0 + 64 + tx * 4);
#pragma unroll
    for (int i = 0; i < 8; i++) {
        const int m = m0 + ((i < 4) ? (ty * 4 + i) : (64 + ty * 4 + (i - 4)));
        float* op = h + (size_t)m * D_SAE + s0;
        float4 v0, v1;
        v0.x = fmaxf(acc[i][0] + bv[0], 0.f);
        v0.y = fmaxf(acc[i][1] + bv[1], 0.f);
        v0.z = fmaxf(acc[i][2] + bv[2], 0.f);
        v0.w = fmaxf(acc[i][3] + bv[3], 0.f);
        v1.x = fmaxf(acc[i][4] + bv[4], 0.f);
        v1.y = fmaxf(acc[i][5] + bv[5], 0.f);
        v1.z = fmaxf(acc[i][6] + bv[6], 0.f);
        v1.w = fmaxf(acc[i][7] + bv[7], 0.f);
        *(float4*)(op + tx * 4)      = v0;
        *(float4*)(op + 64 + tx * 4) = v1;
    }
}

// ---------------------------------------------------------------------------
// Kernel 3: per-row top-K_SEL CANDIDATE selection via 4-pass radix select
// on float bits (all values >= 0 so uint order == value order).
// Selects all values >= T where T is the K_SEL-th largest bit pattern
// (count may slightly exceed K_SEL on exact ties; buffer K_BUF).
// ---------------------------------------------------------------------------
__global__ __launch_bounds__(256)
void topk_cand_kernel(const float* __restrict__ h)
{
    const int row = blockIdx.x;
    const int tid = threadIdx.x;
    const float* hrow = h + (size_t)row * D_SAE;

    unsigned int v[64];
#pragma unroll
    for (int i = 0; i < 64; i++)
        v[i] = __float_as_uint(hrow[i * 256 + tid]);

    __shared__ int hist[256];
    __shared__ unsigned int sh_prefix;
    __shared__ int sh_k;

    unsigned int prefix = 0;
    int k = K_SEL;

#pragma unroll
    for (int p = 0; p < 4; p++) {
        const unsigned int himask =
            (p == 0) ? 0u :
            (p == 1) ? 0xFF000000u :
            (p == 2) ? 0xFFFF0000u : 0xFFFFFF00u;
        const int sh = 24 - 8 * p;

        hist[tid] = 0;
        __syncthreads();
#pragma unroll
        for (int i = 0; i < 64; i++) {
            const unsigned int b = v[i];
            if (((b ^ prefix) & himask) == 0)
                atomicAdd(&hist[(b >> sh) & 255], 1);
        }
        __syncthreads();
        if (tid == 0) {
            int cum = 0;
            int bin = 255;
            for (; bin >= 0; bin--) {
                const int c = hist[bin];
                if (cum + c >= k) { sh_k = k - cum; break; }
                cum += c;
            }
            sh_prefix = prefix | ((unsigned int)bin << sh);
        }
        __syncthreads();
        prefix = sh_prefix;
        k = sh_k;
        __syncthreads();
    }

    const unsigned int T = prefix;   // K_SEL-th largest bit pattern

    unsigned long long selmask = 0ull;
#pragma unroll
    for (int i = 0; i < 64; i++)
        if (v[i] >= T) selmask |= (1ull << i);

    // deterministic compaction (tid-major order)
    const int lane = tid & 31;
    const int wid  = tid >> 5;
    const int cnt = __popcll(selmask);
    int incl = cnt;
#pragma unroll
    for (int off = 1; off < 32; off <<= 1) {
        const int t = __shfl_up_sync(0xFFFFFFFFu, incl, off);
        if (lane >= off) incl += t;
    }
    __shared__ int wsum[8];
    if (lane == 31) wsum[wid] = incl;
    __syncthreads();
    int woff = 0;
    for (int w = 0; w < wid; w++) woff += wsum[w];
    int slot = woff + incl - cnt;

    if (tid == 0) {
        int tot = 0;
        for (int w = 0; w < 8; w++) tot += wsum[w];
        g_cand_cnt[row] = (tot > K_BUF) ? K_BUF : tot;
    }

#pragma unroll
    for (int i = 0; i < 64; i++) {
        if ((selmask >> i) & 1ull) {
            if (slot < K_BUF)
                g_cand_idx[(size_t)row * K_BUF + slot] = i * 256 + tid;
            slot++;
        }
    }
}

// ---------------------------------------------------------------------------
// Kernel 4: exact refinement. For each row, recompute the candidate dots
// in fp64 (exact), apply the reference's rounding (f32(dot) + b, relu),
// rank by (value desc, index asc), keep top-64, zero the h row and
// scatter the exact values. Also fills g_tk_{idx,val} for the decoder.
// ---------------------------------------------------------------------------
__global__ __launch_bounds__(256)
void refine_kernel(const float* __restrict__ x,
                   const float* __restrict__ W,
                   const float* __restrict__ bias,
                   float* __restrict__ h)
{
    const int row = blockIdx.x;
    const int tid = threadIdx.x;
    const int lane = tid & 31;
    const int wid  = tid >> 5;

    __shared__ float sx[D_MODEL];
    __shared__ int      scand[K_BUF];
    __shared__ float    sval[K_BUF];
    __shared__ unsigned skey[K_BUF];

    const int cnt = g_cand_cnt[row];

    // load x row into smem (1024 floats = 256 x float4)
    {
        const float4 xv = ((const float4*)(x + (size_t)row * D_MODEL))[tid];
        ((float4*)sx)[tid] = xv;
    }
    if (tid < cnt) scand[tid] = g_cand_idx[(size_t)row * K_BUF + tid];
    __syncthreads();

    // one warp per candidate, round-robin
    for (int c = wid; c < cnt; c += 8) {
        const int f = scand[c];
        const float4* w4 = (const float4*)(W + (size_t)f * D_MODEL);
        const float4* x4 = (const float4*)sx;
        double acc = 0.0;
#pragma unroll
        for (int i = lane; i < D_MODEL / 4; i += 32) {
            const float4 wv = w4[i];
            const float4 xv = x4[i];
            acc += (double)xv.x * (double)wv.x;
            acc += (double)xv.y * (double)wv.y;
            acc += (double)xv.z * (double)wv.z;
            acc += (double)xv.w * (double)wv.w;
        }
#pragma unroll
        for (int off = 16; off > 0; off >>= 1)
            acc += __shfl_down_sync(0xFFFFFFFFu, acc, off);
        if (lane == 0) {
            const float dotf = (float)acc;           // round like reference
            const float vv = fmaxf(dotf + bias[f], 0.0f);
            sval[c] = vv;
            skey[c] = __float_as_uint(vv);
        }
    }
    __syncthreads();

    // zero h row
    {
        float4* hrow4 = (float4*)(h + (size_t)row * D_SAE);
        const float4 z = make_float4(0.f, 0.f, 0.f, 0.f);
#pragma unroll
        for (int i = 0; i < D_SAE / 4 / 256; i++)
            hrow4[i * 256 + tid] = z;
    }
    __syncthreads();

    // rank candidates: value desc, index asc (jax top_k tie rule)
    if (tid < cnt) {
        const unsigned mykey = skey[tid];
        const int      myidx = scand[tid];
        int rank = 0;
        for (int j = 0; j < cnt; j++) {
            const unsigned kj = skey[j];
            if (kj > mykey || (kj == mykey && scand[j] < myidx)) rank++;
        }
        if (rank < K_TOP) {
            const float vv = sval[tid];
            g_tk_idx[row * K_TOP + rank] = myidx;
            g_tk_val[row * K_TOP + rank] = vv;
            h[(size_t)row * D_SAE + myidx] = vv;
        }
    }
}

// ---------------------------------------------------------------------------
// Kernel 5: sparse decoder  recon[n,:] = sum_j val_j * WdT[idx_j, :]
// ---------------------------------------------------------------------------
__global__ __launch_bounds__(256)
void decoder_kernel(float* __restrict__ recon)
{
    const int n = blockIdx.x;
    const int tid = threadIdx.x;
    __shared__ int   sidx[K_TOP];
    __shared__ float svals[K_TOP];
    if (tid < K_TOP) {
        sidx[tid] = g_tk_idx[n * K_TOP + tid];
        svals[tid] = g_tk_val[n * K_TOP + tid];
    }
    __syncthreads();

    float4 acc = make_float4(0.f, 0.f, 0.f, 0.f);
    const int d4 = tid * 4;
#pragma unroll 8
    for (int j = 0; j < K_TOP; j++) {
        const float vv = svals[j];
        const float4 w = *(const float4*)(g_WdT + (size_t)sidx[j] * D_MODEL + d4);
        acc.x = fmaf(vv, w.x, acc.x);
        acc.y = fmaf(vv, w.y, acc.y);
        acc.z = fmaf(vv, w.z, acc.z);
        acc.w = fmaf(vv, w.w, acc.w);
    }
    *(float4*)(recon + (size_t)n * D_MODEL + d4) = acc;
}

// ---------------------------------------------------------------------------
// Launch
// ---------------------------------------------------------------------------
extern "C" void kernel_launch(void* const* d_in, const int* in_sizes, int n_in,
                              void* d_out, int out_size)
{
    (void)in_sizes; (void)n_in; (void)out_size;
    const float* x     = (const float*)d_in[0];
    const float* W_enc = (const float*)d_in[1];
    const float* b_enc = (const float*)d_in[2];
    const float* W_dec = (const float*)d_in[3];

    float* out   = (float*)d_out;
    float* recon = out;                                  // [8192, 1024]
    float* h     = out + (size_t)NROWS * D_MODEL;        // [8192, 16384]

    transpose_kernel<<<dim3(D_SAE / 32, D_MODEL / 32), dim3(32, 8)>>>(W_dec);
    encoder_gemm_kernel<<<dim3(D_SAE / 128, NROWS / 128), 256>>>(x, W_enc, b_enc, h);
    topk_cand_kernel<<<NROWS, 256>>>(h);
    refine_kernel<<<NROWS, 256>>>(x, W_enc, b_enc, h);
    decoder_kernel<<<NROWS, 256>>>(recon);
}

// round 4
// speedup vs baseline: 6.0318x; 6.0318x over previous
#include <cuda_runtime.h>
#include <cuda_bf16.h>
#include <cstdint>

// ---------------------------------------------------------------------------
// Problem constants
// ---------------------------------------------------------------------------
constexpr int D_MODEL = 1024;
constexpr int D_SAE   = 16384;
constexpr int NROWS   = 8192;
constexpr int K_TOP   = 64;
constexpr int K_SEL   = 100;   // candidate pool for exact re-ranking
constexpr int K_BUF   = 128;   // candidate buffer (bf16 ties can exceed K_SEL)

// ---------------------------------------------------------------------------
// Scratch (static __device__ arrays — no runtime allocation)
// ---------------------------------------------------------------------------
__device__ float         g_WdT[(size_t)D_SAE * D_MODEL];    // 64 MB
__device__ __nv_bfloat16 g_x16[(size_t)NROWS * D_MODEL];    // 16 MB
__device__ __nv_bfloat16 g_W16[(size_t)D_SAE * D_MODEL];    // 32 MB
__device__ __nv_bfloat16 g_h16[(size_t)NROWS * D_SAE];      // 256 MB
__device__ int           g_cand_idx[(size_t)NROWS * K_BUF];
__device__ int           g_cand_cnt[NROWS];
__device__ int           g_tk_idx[NROWS * K_TOP];
__device__ float         g_tk_val[NROWS * K_TOP];

// ---------------------------------------------------------------------------
// Helpers
// ---------------------------------------------------------------------------
__device__ __forceinline__ uint32_t smem_u32(const void* p) {
    uint32_t a;
    asm("{ .reg .u64 t; cvta.to.shared.u64 t, %1; cvt.u32.u64 %0, t; }"
        : "=r"(a) : "l"(p));
    return a;
}

__device__ __forceinline__ uint32_t pack_bf16x2(float a, float b) {
    __nv_bfloat162 p = __floats2bfloat162_rn(a, b);
    return *reinterpret_cast<uint32_t*>(&p);
}

#define LDSM_X4(r0, r1, r2, r3, addr) \
    asm volatile("ldmatrix.sync.aligned.m8n8.x4.shared.b16 {%0,%1,%2,%3}, [%4];" \
                 : "=r"(r0), "=r"(r1), "=r"(r2), "=r"(r3) : "r"(addr))

#define MMA16816(d, a, b0_, b1_) \
    asm volatile("mma.sync.aligned.m16n8k16.row.col.f32.bf16.bf16.f32 " \
                 "{%0,%1,%2,%3}, {%4,%5,%6,%7}, {%8,%9}, {%0,%1,%2,%3};" \
                 : "+f"((d)[0]), "+f"((d)[1]), "+f"((d)[2]), "+f"((d)[3]) \
                 : "r"((a)[0]), "r"((a)[1]), "r"((a)[2]), "r"((a)[3]), \
                   "r"(b0_), "r"(b1_))

// ---------------------------------------------------------------------------
// Kernels 1a/1b: f32 -> bf16 conversion of x and W_enc
// ---------------------------------------------------------------------------
__global__ void cvt_x_kernel(const float* __restrict__ src) {
    const int i = blockIdx.x * 256 + threadIdx.x;
    const float4 v = ((const float4*)src)[i];
    ((uint2*)g_x16)[i] = make_uint2(pack_bf16x2(v.x, v.y), pack_bf16x2(v.z, v.w));
}
__global__ void cvt_w_kernel(const float* __restrict__ src) {
    const int i = blockIdx.x * 256 + threadIdx.x;
    const float4 v = ((const float4*)src)[i];
    ((uint2*)g_W16)[i] = make_uint2(pack_bf16x2(v.x, v.y), pack_bf16x2(v.z, v.w));
}

// ---------------------------------------------------------------------------
// Kernel 2: W_dec [D_MODEL, D_SAE] -> g_WdT [D_SAE, D_MODEL]
// ---------------------------------------------------------------------------
__global__ void transpose_kernel(const float* __restrict__ Wd) {
    __shared__ float tile[32][33];
    const int tx = threadIdx.x, ty = threadIdx.y;
    const int s0 = blockIdx.x * 32, d0 = blockIdx.y * 32;
#pragma unroll
    for (int j = ty; j < 32; j += 8)
        tile[j][tx] = Wd[(size_t)(d0 + j) * D_SAE + (s0 + tx)];
    __syncthreads();
#pragma unroll
    for (int j = ty; j < 32; j += 8)
        g_WdT[(size_t)(s0 + j) * D_MODEL + (d0 + tx)] = tile[tx][j];
}

// ---------------------------------------------------------------------------
// Kernel 3: bf16 HMMA encoder GEMM (approximate, for candidate selection)
// h16[n,s] = bf16( relu( x16[n,:]·W16[s,:] + bias[s] ) )
// BM=128, BN=128, BK=64; 8 warps (2x4), warp tile 64x32; mma.sync m16n8k16.
// smem rows padded to 72 bf16 (144B) -> conflict-free ldmatrix.
// ---------------------------------------------------------------------------
constexpr int SSTRIDE    = 72;                         // bf16 elems per smem row
constexpr int TILE_BYTES = 128 * SSTRIDE * 2;          // 18432 per operand tile
constexpr int SMG_A0 = 0;
constexpr int SMG_B0 = TILE_BYTES;
constexpr int SMG_A1 = 2 * TILE_BYTES;
constexpr int SMG_B1 = 3 * TILE_BYTES;
constexpr int SMG_BIAS = 4 * TILE_BYTES;               // 128 f32
constexpr int SMG_TOTAL = SMG_BIAS + 512;

__global__ __launch_bounds__(256)
void gemm_hmma_kernel(const float* __restrict__ bias) {
    extern __shared__ __align__(16) char smem[];
    const uint32_t sb = smem_u32(smem);
    const int tid  = threadIdx.x;
    const int lane = tid & 31;
    const int warp = tid >> 5;
    const int warpM = warp >> 2;        // 0..1
    const int warpN = warp & 3;         // 0..3
    const int m0 = blockIdx.y * 128;
    const int s0 = blockIdx.x * 128;

    float* biasSm = (float*)(smem + SMG_BIAS);
    if (tid < 128) biasSm[tid] = bias[s0 + tid];

    const __nv_bfloat16* Ag = g_x16 + (size_t)m0 * D_MODEL;
    const __nv_bfloat16* Bg = g_W16 + (size_t)s0 * D_MODEL;

    // global-load / smem-store indices (8 rows-of-16B per thread per operand)
    const int grow = tid >> 1;              // 0..127
    const int gc16a = (tid & 1) * 4;        // which 16B chunk base (0 or 4)

    float acc[4][4][4];
#pragma unroll
    for (int i = 0; i < 4; i++)
#pragma unroll
        for (int j = 0; j < 4; j++)
#pragma unroll
            for (int q = 0; q < 4; q++) acc[i][j][q] = 0.f;

    // ldmatrix lane-address components
    const int a_r = warpM * 64 + (lane & 15);          // + mi*16
    const int a_k = (lane >> 4) * 8;
    const int b_r = warpN * 32 + (lane & 7) + ((lane >> 4) << 3);  // + nj*16
    const int b_k = ((lane >> 3) & 1) * 8;

    uint4 pa[4], pb[4];

    auto g_load = [&](int kt) {
#pragma unroll
        for (int it = 0; it < 4; it++) {
            const int idx = it * 256 + tid;
            const int row = idx >> 3, c16 = idx & 7;
            pa[it] = *(const uint4*)(Ag + (size_t)row * D_MODEL + kt * 64 + c16 * 8);
            pb[it] = *(const uint4*)(Bg + (size_t)row * D_MODEL + kt * 64 + c16 * 8);
        }
    };
    auto s_store = [&](int aoff, int boff) {
#pragma unroll
        for (int it = 0; it < 4; it++) {
            const int idx = it * 256 + tid;
            const int row = idx >> 3, c16 = idx & 7;
            *(uint4*)(smem + aoff + row * (SSTRIDE * 2) + c16 * 16) = pa[it];
            *(uint4*)(smem + boff + row * (SSTRIDE * 2) + c16 * 16) = pb[it];
        }
    };

    g_load(0);
    s_store(SMG_A0, SMG_B0);
    __syncthreads();

    for (int kt = 0; kt < 16; kt++) {
        const int buf = kt & 1;
        const uint32_t abase = sb + (buf ? SMG_A1 : SMG_A0);
        const uint32_t bbase = sb + (buf ? SMG_B1 : SMG_B0);

        if (kt + 1 < 16) g_load(kt + 1);

#pragma unroll
        for (int kk = 0; kk < 4; kk++) {
            uint32_t af[4][4];
#pragma unroll
            for (int mi = 0; mi < 4; mi++) {
                const uint32_t addr =
                    abase + ((a_r + mi * 16) * SSTRIDE + kk * 16 + a_k) * 2;
                LDSM_X4(af[mi][0], af[mi][1], af[mi][2], af[mi][3], addr);
            }
            uint32_t bf[2][4];
#pragma unroll
            for (int nj = 0; nj < 2; nj++) {
                const uint32_t addr =
                    bbase + ((b_r + nj * 16) * SSTRIDE + kk * 16 + b_k) * 2;
                LDSM_X4(bf[nj][0], bf[nj][1], bf[nj][2], bf[nj][3], addr);
            }
#pragma unroll
            for (int mi = 0; mi < 4; mi++)
#pragma unroll
                for (int n8 = 0; n8 < 4; n8++)
                    MMA16816(acc[mi][n8], af[mi],
                             bf[n8 >> 1][(n8 & 1) * 2],
                             bf[n8 >> 1][(n8 & 1) * 2 + 1]);
        }

        if (kt + 1 < 16) {
            s_store(buf ? SMG_A0 : SMG_A1, buf ? SMG_B0 : SMG_B1);
            __syncthreads();
        }
    }

    // epilogue: bias + relu + bf16 store
#pragma unroll
    for (int mi = 0; mi < 4; mi++) {
        const int r0 = m0 + warpM * 64 + mi * 16 + (lane >> 2);
        __nv_bfloat16* h0 = g_h16 + (size_t)r0 * D_SAE;
        __nv_bfloat16* h1 = h0 + (size_t)8 * D_SAE;
#pragma unroll
        for (int n8 = 0; n8 < 4; n8++) {
            const int cl = warpN * 32 + n8 * 8 + 2 * (lane & 3);
            const float bv0 = biasSm[cl], bv1 = biasSm[cl + 1];
            const int col = s0 + cl;
            *(uint32_t*)(h0 + col) = pack_bf16x2(fmaxf(acc[mi][n8][0] + bv0, 0.f),
                                                 fmaxf(acc[mi][n8][1] + bv1, 0.f));
            *(uint32_t*)(h1 + col) = pack_bf16x2(fmaxf(acc[mi][n8][2] + bv0, 0.f),
                                                 fmaxf(acc[mi][n8][3] + bv1, 0.f));
        }
    }
}

// ---------------------------------------------------------------------------
// Kernel 4: per-row top-K_SEL candidate selection (radix on bf16 bits, 2 passes)
// All values >= 0 so u16 bit order == value order.
// ---------------------------------------------------------------------------
__global__ __launch_bounds__(256)
void topk_cand_kernel() {
    const int row = blockIdx.x;
    const int tid = threadIdx.x;
    const uint32_t* hrow = (const uint32_t*)(g_h16 + (size_t)row * D_SAE);

    uint32_t v[32];
#pragma unroll
    for (int j = 0; j < 32; j++) v[j] = hrow[j * 256 + tid];

    __shared__ int hist[256];
    __shared__ unsigned sh_prefix;
    __shared__ int sh_k;

    unsigned prefix = 0;
    int k = K_SEL;

#pragma unroll
    for (int p = 0; p < 2; p++) {
        hist[tid] = 0;
        __syncthreads();
#pragma unroll
        for (int j = 0; j < 32; j++) {
            const uint32_t w2 = v[j];
#pragma unroll
            for (int hh = 0; hh < 2; hh++) {
                const unsigned key = (w2 >> (16 * hh)) & 0xFFFFu;
                if (p == 0)
                    atomicAdd(&hist[key >> 8], 1);
                else if ((key >> 8) == (prefix >> 8))
                    atomicAdd(&hist[key & 255], 1);
            }
        }
        __syncthreads();
        if (tid == 0) {
            int cum = 0, bin = 255;
            for (; bin >= 0; bin--) {
                const int cc = hist[bin];
                if (cum + cc >= k) { sh_k = k - cum; break; }
                cum += cc;
            }
            sh_prefix = prefix | ((unsigned)bin << (8 * (1 - p)));
        }
        __syncthreads();
        prefix = sh_prefix;
        k = sh_k;
        __syncthreads();
    }

    const unsigned T = prefix;   // K_SEL-th largest bf16 bit pattern

    unsigned long long selmask = 0ull;
#pragma unroll
    for (int j = 0; j < 32; j++) {
        const uint32_t w2 = v[j];
        if ((w2 & 0xFFFFu) >= T)  selmask |= (1ull << (2 * j));
        if ((w2 >> 16)     >= T)  selmask |= (1ull << (2 * j + 1));
    }

    // deterministic compaction (tid-major)
    const int lane = tid & 31;
    const int wid  = tid >> 5;
    const int cnt = __popcll(selmask);
    int incl = cnt;
#pragma unroll
    for (int off = 1; off < 32; off <<= 1) {
        const int t = __shfl_up_sync(0xFFFFFFFFu, incl, off);
        if (lane >= off) incl += t;
    }
    __shared__ int wsum[8];
    if (lane == 31) wsum[wid] = incl;
    __syncthreads();
    int woff = 0;
    for (int ww = 0; ww < wid; ww++) woff += wsum[ww];
    int slot = woff + incl - cnt;

    if (tid == 0) {
        int tot = 0;
        for (int ww = 0; ww < 8; ww++) tot += wsum[ww];
        g_cand_cnt[row] = (tot > K_BUF) ? K_BUF : tot;
    }

#pragma unroll
    for (int j = 0; j < 32; j++) {
#pragma unroll
        for (int hh = 0; hh < 2; hh++) {
            if ((selmask >> (2 * j + hh)) & 1ull) {
                if (slot < K_BUF)
                    g_cand_idx[(size_t)row * K_BUF + slot] = 2 * (j * 256 + tid) + hh;
                slot++;
            }
        }
    }
}

// ---------------------------------------------------------------------------
// Kernel 5: exact fp32 refinement of candidates + h scatter
// ---------------------------------------------------------------------------
__global__ __launch_bounds__(256)
void refine_kernel(const float* __restrict__ x,
                   const float* __restrict__ W,
                   const float* __restrict__ bias,
                   float* __restrict__ h) {
    const int row = blockIdx.x;
    const int tid = threadIdx.x;
    const int lane = tid & 31;
    const int wid  = tid >> 5;

    __shared__ float    sx[D_MODEL];
    __shared__ int      scand[K_BUF];
    __shared__ float    sval[K_BUF];
    __shared__ unsigned skey[K_BUF];

    const int cnt = g_cand_cnt[row];

    ((float4*)sx)[tid] = ((const float4*)(x + (size_t)row * D_MODEL))[tid];
    if (tid < cnt) scand[tid] = g_cand_idx[(size_t)row * K_BUF + tid];
    __syncthreads();

    // warp per candidate: fp32 split-sum dot (32 partials + tree), near-exact
    for (int c = wid; c < cnt; c += 8) {
        const int f = scand[c];
        const float4* w4 = (const float4*)(W + (size_t)f * D_MODEL);
        const float4* x4 = (const float4*)sx;
        float acc = 0.f;
#pragma unroll
        for (int i = lane; i < D_MODEL / 4; i += 32) {
            const float4 wv = w4[i];
            const float4 xv = x4[i];
            acc = fmaf(xv.x, wv.x, acc);
            acc = fmaf(xv.y, wv.y, acc);
            acc = fmaf(xv.z, wv.z, acc);
            acc = fmaf(xv.w, wv.w, acc);
        }
#pragma unroll
        for (int off = 16; off > 0; off >>= 1)
            acc += __shfl_down_sync(0xFFFFFFFFu, acc, off);
        if (lane == 0) {
            const float vv = fmaxf(acc + bias[f], 0.0f);
            sval[c] = vv;
            skey[c] = __float_as_uint(vv);
        }
    }
    __syncthreads();

    // zero the output h row
    {
        float4* hrow4 = (float4*)(h + (size_t)row * D_SAE);
        const float4 z = make_float4(0.f, 0.f, 0.f, 0.f);
#pragma unroll
        for (int i = 0; i < D_SAE / 4 / 256; i++)
            hrow4[i * 256 + tid] = z;
    }
    __syncthreads();

    // rank (value desc, index asc) and scatter top-64
    if (tid < cnt) {
        const unsigned mykey = skey[tid];
        const int      myidx = scand[tid];
        int rank = 0;
        for (int j = 0; j < cnt; j++) {
            const unsigned kj = skey[j];
            if (kj > mykey || (kj == mykey && scand[j] < myidx)) rank++;
        }
        if (rank < K_TOP) {
            const float vv = sval[tid];
            g_tk_idx[row * K_TOP + rank] = myidx;
            g_tk_val[row * K_TOP + rank] = vv;
            h[(size_t)row * D_SAE + myidx] = vv;
        }
    }
}

// ---------------------------------------------------------------------------
// Kernel 6: sparse decoder  recon[n,:] = sum_j val_j * WdT[idx_j, :]
// ---------------------------------------------------------------------------
__global__ __launch_bounds__(256)
void decoder_kernel(float* __restrict__ recon) {
    const int n = blockIdx.x;
    const int tid = threadIdx.x;
    __shared__ int   sidx[K_TOP];
    __shared__ float svals[K_TOP];
    if (tid < K_TOP) {
        sidx[tid]  = g_tk_idx[n * K_TOP + tid];
        svals[tid] = g_tk_val[n * K_TOP + tid];
    }
    __syncthreads();

    float4 acc = make_float4(0.f, 0.f, 0.f, 0.f);
    const int d4 = tid * 4;
#pragma unroll 8
    for (int j = 0; j < K_TOP; j++) {
        const float vv = svals[j];
        const float4 w = *(const float4*)(g_WdT + (size_t)sidx[j] * D_MODEL + d4);
        acc.x = fmaf(vv, w.x, acc.x);
        acc.y = fmaf(vv, w.y, acc.y);
        acc.z = fmaf(vv, w.z, acc.z);
        acc.w = fmaf(vv, w.w, acc.w);
    }
    *(float4*)(recon + (size_t)n * D_MODEL + d4) = acc;
}

// ---------------------------------------------------------------------------
// Launch
// ---------------------------------------------------------------------------
extern "C" void kernel_launch(void* const* d_in, const int* in_sizes, int n_in,
                              void* d_out, int out_size) {
    (void)in_sizes; (void)n_in; (void)out_size;
    const float* x     = (const float*)d_in[0];
    const float* W_enc = (const float*)d_in[1];
    const float* b_enc = (const float*)d_in[2];
    const float* W_dec = (const float*)d_in[3];

    float* out   = (float*)d_out;
    float* recon = out;                              // [8192, 1024]
    float* h     = out + (size_t)NROWS * D_MODEL;    // [8192, 16384]

    cudaFuncSetAttribute(gemm_hmma_kernel,
                         cudaFuncAttributeMaxDynamicSharedMemorySize, SMG_TOTAL);

    cvt_x_kernel<<<NROWS * D_MODEL / 4 / 256, 256>>>(x);
    cvt_w_kernel<<<(int)((size_t)D_SAE * D_MODEL / 4 / 256), 256>>>(W_enc);
    transpose_kernel<<<dim3(D_SAE / 32, D_MODEL / 32), dim3(32, 8)>>>(W_dec);
    gemm_hmma_kernel<<<dim3(D_SAE / 128, NROWS / 128), 256, SMG_TOTAL>>>(b_enc);
    topk_cand_kernel<<<NROWS, 256>>>();
    refine_kernel<<<NROWS, 256>>>(x, W_enc, b_enc, h);
    decoder_kernel<<<NROWS, 256>>>(recon);
}